// round 17
// baseline (speedup 1.0000x reference)
#include <cuda_runtime.h>

// Shapes fixed by the problem: B=4, T=2048, D=768 -> E=2*D=1536, H=256.
#define B_DIM 4
#define T_DIM 2048
#define E_DIM 1536
#define H_DIM 256

#define COLS4     (E_DIM / 4)              // 384 float4 per (b,t) row
#define N_BLOCKS  296                      // 148 SMs x 2, single wave
#define N_BIG     56                       // blocks 0..55: 6 sub-chunks; rest: 5
#define SC_TOTAL  1536                     // 6 colchunks x 256 row-groups
#define N_TAIL    16
#define TAIL_BASE (N_BLOCKS - N_TAIL)      // 280 (tail = light 5-chunk blocks)
#define D_CHUNK   (E_DIM / N_TAIL)         // 96 scalar columns per tail block

// Sub-chunk sc = cc*256 + rg: colchunk cc in [0,6), row-group rg in [0,256)
// covering rows rg*8..rg*8+8 of the 256 (b,c4) slots [cc*256, cc*256+256).
// base_sc(i) = i<56 ? 6i : 5i+56  (monotone; partition of [0,1536)).

// Scratch: __device__ globals (allocation-free rule).
// g_part: 2 flush slots per block (slot f covers colchunk cc0(i)+f); both
// written EVERY call (zeros if slot 1 unused) -> fully overwritten, no reset.
__device__ float4            g_part[N_BLOCKS][2][256];   // 2.4 MB
__device__ float             g_hpart[N_TAIL][B_DIM][H_DIM];
__device__ volatile unsigned g_c1;
__device__ unsigned          g_c2;

__global__ void __launch_bounds__(256, 2)
curiosity_fused(const float* __restrict__ x,
                const float* __restrict__ W1,
                const float* __restrict__ b1,
                const float* __restrict__ W2,
                const float* __restrict__ b2,
                float* __restrict__ out, int out_size) {
    const int tid = threadIdx.x;
    const int bid = blockIdx.x;

    // ---------------- Phase 1: balanced column sum (all 296 blocks) --------
    {
        const int base = (bid < N_BIG) ? 6 * bid : 5 * bid + N_BIG;
        const int nsc  = (bid < N_BIG) ? 6 : 5;
        const float4* X4 = reinterpret_cast<const float4*>(x);

        float4 acc = make_float4(0.f, 0.f, 0.f, 0.f);
        int cur_cc = base >> 8;
        int f = 0;

        for (int k = 0; k < nsc; k++) {
            const int sc = base + k;
            const int cc = sc >> 8;
            if (cc != cur_cc) {            // at most once per block
                g_part[bid][0][tid] = acc;
                acc = make_float4(0.f, 0.f, 0.f, 0.f);
                cur_cc = cc;
                f = 1;
            }
            const int rg = sc & 255;
            const int gc = cc * 256 + tid; // (b, c4) slot
            const int b  = gc / COLS4;
            const int c4 = gc % COLS4;
            const float4* p = X4 + (size_t)(b * T_DIM + rg * 8) * COLS4 + c4;

            // 8 independent evict-first loads in flight (R2 batching + R16 hint).
            float4 v0 = __ldcs(p + 0 * COLS4);
            float4 v1 = __ldcs(p + 1 * COLS4);
            float4 v2 = __ldcs(p + 2 * COLS4);
            float4 v3 = __ldcs(p + 3 * COLS4);
            float4 v4 = __ldcs(p + 4 * COLS4);
            float4 v5 = __ldcs(p + 5 * COLS4);
            float4 v6 = __ldcs(p + 6 * COLS4);
            float4 v7 = __ldcs(p + 7 * COLS4);
            acc.x += ((v0.x + v1.x) + (v2.x + v3.x)) + ((v4.x + v5.x) + (v6.x + v7.x));
            acc.y += ((v0.y + v1.y) + (v2.y + v3.y)) + ((v4.y + v5.y) + (v6.y + v7.y));
            acc.z += ((v0.z + v1.z) + (v2.z + v3.z)) + ((v4.z + v5.z) + (v6.z + v7.z));
            acc.w += ((v0.w + v1.w) + (v2.w + v3.w)) + ((v4.w + v5.w) + (v6.w + v7.w));
        }

        g_part[bid][f][tid] = acc;
        if (f == 0)
            g_part[bid][1][tid] = make_float4(0.f, 0.f, 0.f, 0.f);

        __syncthreads();                   // all block stores issued
        if (tid == 0) {
            __threadfence();               // release partials before counter
            atomicAdd((unsigned*)&g_c1, 1u);
        }
    }

    // 280 non-tail blocks exit immediately.
    if (bid < TAIL_BASE) return;
    const int ti = bid - TAIL_BASE;        // tail index 0..15

    // ---------------- Phase 2: GEMV1 tail (16 blocks x 96 W1 rows) ---------
    __shared__ float s[B_DIM][D_CHUNK];
    const int j  = tid;                    // hidden index, 256 threads = H
    const int d0 = ti * D_CHUNK;

    // Preload W1 chunk into registers BEFORE spinning (overlaps the stream).
    float w[D_CHUNK];
#pragma unroll
    for (int dd = 0; dd < D_CHUNK; dd++)
        w[dd] = W1[(size_t)(d0 + dd) * H_DIM + j];

    if (tid == 0) {
        while (g_c1 < N_BLOCKS) { }        // volatile poll
        __threadfence();                   // acquire
    }
    __syncthreads();

    // Gather: threads 0..95 each own one float4 column slot gcv.
    // Contributors to colchunk cc: blocks with cc0==cc (slot 0) and
    // cc0==cc-1 (slot 1; zeros if that block never crossed).
    if (tid < B_DIM * (D_CHUNK / 4)) {     // 96 threads
        const int b   = tid / (D_CHUNK / 4);
        const int c4l = tid % (D_CHUNK / 4);
        const int gcv = b * COLS4 + (d0 >> 2) + c4l;  // float4 slot in [0,1536)
        const int cc   = gcv >> 8;
        const int lane = gcv & 255;

        float4 sum = make_float4(0.f, 0.f, 0.f, 0.f);
        for (int i = 0; i < N_BLOCKS; i++) {
            const int base = (i < N_BIG) ? 6 * i : 5 * i + N_BIG;
            const int cc0  = base >> 8;
            if (cc0 == cc) {
                float4 v = g_part[i][0][lane];
                sum.x += v.x; sum.y += v.y; sum.z += v.z; sum.w += v.w;
            } else if (cc0 + 1 == cc) {
                float4 v = g_part[i][1][lane];
                sum.x += v.x; sum.y += v.y; sum.z += v.z; sum.w += v.w;
            }
        }
        const float inv = 1.0f / (float)T_DIM;
        s[b][c4l * 4 + 0] = sum.x * inv;
        s[b][c4l * 4 + 1] = sum.y * inv;
        s[b][c4l * 4 + 2] = sum.z * inv;
        s[b][c4l * 4 + 3] = sum.w * inv;
    }
    __syncthreads();

    float a0 = 0.f, a1 = 0.f, a2 = 0.f, a3 = 0.f;
#pragma unroll
    for (int dd = 0; dd < D_CHUNK; dd++) {
        float ww = w[dd];
        a0 = fmaf(s[0][dd], ww, a0);
        a1 = fmaf(s[1][dd], ww, a1);
        a2 = fmaf(s[2][dd], ww, a2);
        a3 = fmaf(s[3][dd], ww, a3);
    }
    g_hpart[ti][0][j] = a0;
    g_hpart[ti][1][j] = a1;
    g_hpart[ti][2][j] = a2;
    g_hpart[ti][3][j] = a3;

    // ---------------- Phase 3: epilogue in the LAST-arriving tail block ----
    __syncthreads();
    __shared__ unsigned s_last;
    if (tid == 0) {
        __threadfence();                   // release hidden partials
        s_last = (atomicAdd(&g_c2, 1u) == N_TAIL - 1u) ? 1u : 0u;
    }
    __syncthreads();
    if (!s_last) return;

    if (tid == 0) __threadfence();         // acquire all hidden partials
    __syncthreads();

    __shared__ float red[B_DIM][8];
    {
        const int lane = j & 31, warp = j >> 5;
        float w2 = W2[j];
        float bb = b1[j];
        float v[B_DIM];
#pragma unroll
        for (int b = 0; b < B_DIM; b++) {
            float h = bb;
#pragma unroll
            for (int p = 0; p < N_TAIL; p++) h += g_hpart[p][b][j];
            v[b] = fmaxf(h, 0.0f) * w2;
        }
#pragma unroll
        for (int off = 16; off > 0; off >>= 1)
#pragma unroll
            for (int b = 0; b < B_DIM; b++)
                v[b] += __shfl_down_sync(0xffffffffu, v[b], off);
        if (lane == 0)
#pragma unroll
            for (int b = 0; b < B_DIM; b++) red[b][warp] = v[b];
    }
    __syncthreads();

    if (tid < B_DIM && tid < out_size) {
        float sm = 0.f;
#pragma unroll
        for (int w8 = 0; w8 < 8; w8++) sm += red[tid][w8];
        out[tid] = sm + b2[0];
    }
    // best_action_idx slot: argmax over 32 bit-identical entropies == 0
    // always (int 0 == float 0.0 bit pattern). Zero-fill the rest.
    for (int i = B_DIM + tid; i < out_size; i += 256)
        out[i] = 0.0f;

    __syncthreads();
    if (tid == 0) { g_c2 = 0u; g_c1 = 0u; __threadfence(); }
}

extern "C" void kernel_launch(void* const* d_in, const int* in_sizes, int n_in,
                              void* d_out, int out_size) {
    const float* x  = (const float*)d_in[0];
    const float* W1 = (const float*)d_in[1];
    const float* b1 = (const float*)d_in[2];
    const float* W2 = (const float*)d_in[3];
    const float* b2 = (const float*)d_in[4];
    float* out = (float*)d_out;

    curiosity_fused<<<N_BLOCKS, 256>>>(x, W1, b1, W2, b2, out, out_size);
}